// round 2
// baseline (speedup 1.0000x reference)
#include <cuda_runtime.h>

// AOLayer: out[b,n,a] = ang * rad, B=512,N=32,A=256,P=6.
// Round 2: packed f32x2 math on the FMA pipe (2 rows per iteration),
// EX2 stays scalar on MUFU (the hard floor, ~48% -> ~85% target).

#define A_DIM 256
#define P_DIM 6
#define BN_DIM (512 * 32)
#define ROWS_PER_BLOCK 16

typedef unsigned long long u64;

__device__ __forceinline__ u64 pack2(float lo, float hi) {
    u64 r;
    asm("mov.b64 %0, {%1, %2};" : "=l"(r) : "f"(lo), "f"(hi));
    return r;
}
__device__ __forceinline__ void unpack2(u64 v, float& lo, float& hi) {
    asm("mov.b64 {%0, %1}, %2;" : "=f"(lo), "=f"(hi) : "l"(v));
}
__device__ __forceinline__ u64 add2(u64 a, u64 b) {
    u64 r; asm("add.rn.f32x2 %0, %1, %2;" : "=l"(r) : "l"(a), "l"(b)); return r;
}
__device__ __forceinline__ u64 mul2(u64 a, u64 b) {
    u64 r; asm("mul.rn.f32x2 %0, %1, %2;" : "=l"(r) : "l"(a), "l"(b)); return r;
}
__device__ __forceinline__ u64 fma2(u64 a, u64 b, u64 c) {
    u64 r; asm("fma.rn.f32x2 %0, %1, %2, %3;" : "=l"(r) : "l"(a), "l"(b), "l"(c)); return r;
}
__device__ __forceinline__ u64 ex2_2(u64 x) {
    float lo, hi;
    unpack2(x, lo, hi);
    asm("ex2.approx.f32 %0, %1;" : "=f"(lo) : "f"(lo));
    asm("ex2.approx.f32 %0, %1;" : "=f"(hi) : "f"(hi));
    return pack2(lo, hi);
}

__global__ void __launch_bounds__(A_DIM) aolayer_kernel(
    const float* __restrict__ pos,      // [BN, 3]
    const float* __restrict__ centers,  // [A, 3]
    const float* __restrict__ exps,     // [A, P]
    const float* __restrict__ coeffs,   // [A, P]
    const int*   __restrict__ powers,   // [A, 3]
    float* __restrict__ out)            // [BN, A]
{
    const int a = threadIdx.x;

    // ---- per-atom constants (once per block), duplicated into f32x2 pairs ----
    const float cx = centers[a * 3 + 0];
    const float cy = centers[a * 3 + 1];
    const float cz = centers[a * 3 + 2];
    const u64 ncx2 = pack2(-cx, -cx);
    const u64 ncy2 = pack2(-cy, -cy);
    const u64 ncz2 = pack2(-cz, -cz);

    const float NEG_LOG2E = -1.4426950408889634f;
    u64 ep2[P_DIM], co2[P_DIM];
#pragma unroll
    for (int p = 0; p < P_DIM; p++) {
        float e = exps[a * P_DIM + p] * NEG_LOG2E;
        float c = coeffs[a * P_DIM + p];
        ep2[p] = pack2(e, e);
        co2[p] = pack2(c, c);
    }

    const int px = powers[a * 3 + 0];
    const int py = powers[a * 3 + 1];
    const int pz = powers[a * 3 + 2];
    const bool lx = (px >= 1), qx = (px == 2);
    const bool ly = (py >= 1), qy = (py == 2);
    const bool lz = (pz >= 1), qz = (pz == 2);

    const u64 one2 = pack2(1.0f, 1.0f);

    // ---- stage pos rows into shared memory ----
    __shared__ float spos[ROWS_PER_BLOCK * 3];
    const int row0 = blockIdx.x * ROWS_PER_BLOCK;
    if (threadIdx.x < ROWS_PER_BLOCK * 3) {
        spos[threadIdx.x] = pos[row0 * 3 + threadIdx.x];
    }
    __syncthreads();

    float* out_base = out + (size_t)row0 * A_DIM + a;

#pragma unroll
    for (int r = 0; r < ROWS_PER_BLOCK; r += 2) {
        // pack rows r and r+1
        const u64 xp = pack2(spos[r * 3 + 0], spos[r * 3 + 3]);
        const u64 yp = pack2(spos[r * 3 + 1], spos[r * 3 + 4]);
        const u64 zp = pack2(spos[r * 3 + 2], spos[r * 3 + 5]);

        const u64 dxp = add2(xp, ncx2);
        const u64 dyp = add2(yp, ncy2);
        const u64 dzp = add2(zp, ncz2);

        // r2 (packed): dz*dz + dy*dy + dx*dx
        u64 r2p = mul2(dzp, dzp);
        r2p = fma2(dyp, dyp, r2p);
        r2p = fma2(dxp, dxp, r2p);

        // radial: sum_p co[p] * 2^(ep[p]*r2)
        u64 radp = mul2(co2[0], ex2_2(mul2(ep2[0], r2p)));
#pragma unroll
        for (int p = 1; p < P_DIM; p++) {
            radp = fma2(co2[p], ex2_2(mul2(ep2[p], r2p)), radp);
        }

        // angular: (lx?dx:1)*(qx?dx:1) etc. — predicates uniform across the pair
        const u64 fx = mul2(lx ? dxp : one2, qx ? dxp : one2);
        const u64 fy = mul2(ly ? dyp : one2, qy ? dyp : one2);
        const u64 fz = mul2(lz ? dzp : one2, qz ? dzp : one2);
        const u64 angp = mul2(mul2(fx, fy), fz);

        const u64 op = mul2(angp, radp);
        float o0, o1;
        unpack2(op, o0, o1);
        out_base[(size_t)r * A_DIM] = o0;
        out_base[(size_t)(r + 1) * A_DIM] = o1;
    }
}

extern "C" void kernel_launch(void* const* d_in, const int* in_sizes, int n_in,
                              void* d_out, int out_size) {
    const float* pos     = (const float*)d_in[0];
    const float* centers = (const float*)d_in[1];
    const float* exps    = (const float*)d_in[2];
    const float* coeffs  = (const float*)d_in[3];
    const int*   powers  = (const int*)d_in[4];
    float* out = (float*)d_out;

    dim3 grid(BN_DIM / ROWS_PER_BLOCK);  // 1024 blocks
    dim3 block(A_DIM);                   // 256 threads, one per atom
    aolayer_kernel<<<grid, block>>>(pos, centers, exps, coeffs, powers, out);
}